// round 13
// baseline (speedup 1.0000x reference)
#include <cuda_runtime.h>

typedef unsigned int u32;
typedef unsigned long long u64;

#define BB 8
#define HH 320
#define WW 320
#define TT 16
#define HW (HH*WW)            // 102400
#define CAP 163840            // max candidates/image <= 97*97*16 = 150544
#define KSEL 128
#define SURV 8192             // survivor capacity per image per phase
#define MAXK (1ull<<51)
#define IDXM 0x1FFFFFu

// Scratch (device globals; ~23 MB total).
//  ckey = (conf_bits << 21) | idx       (< 2^51)
//  rkey = (rand_mantissa23 << 21) | idx (< 2^44)
__device__ ulonglong2 g_key[(size_t)BB * CAP];
__device__ u64        g_survc[BB * SURV];      // conf survivors (ckey)
__device__ ulonglong2 g_survr[BB * SURV];      // rand survivors (ckey, rkey)
__device__ int g_cnt[BB], g_nc[BB], g_nr[BB];  // zero-init; reset at end of k_select_sum

// ---------------------------------------------------------------------------
// Threefry-2x32 (JAX rotation schedule), host + device.
// ---------------------------------------------------------------------------
__host__ __device__ __forceinline__ void tf2x32(u32 k0, u32 k1, u32 x0, u32 x1,
                                                u32 &o0, u32 &o1)
{
    u32 ks2 = k0 ^ k1 ^ 0x1BD11BDAu;
    x0 += k0; x1 += k1;
#define ROTL32(v,d) (((v)<<(d))|((v)>>(32-(d))))
#define TFR(r) { x0 += x1; x1 = ROTL32(x1,(r)); x1 ^= x0; }
    TFR(13) TFR(15) TFR(26) TFR(6)  x0 += k1;  x1 += ks2 + 1u;
    TFR(17) TFR(29) TFR(16) TFR(24) x0 += ks2; x1 += k0 + 2u;
    TFR(13) TFR(15) TFR(26) TFR(6)  x0 += k0;  x1 += k1 + 3u;
    TFR(17) TFR(29) TFR(16) TFR(24) x0 += k1;  x1 += ks2 + 4u;
    TFR(13) TFR(15) TFR(26) TFR(6)  x0 += ks2; x1 += k0 + 5u;
#undef TFR
#undef ROTL32
    o0 = x0; o1 = x1;
}

struct ImgKeys { u32 k0[BB]; u32 k1[BB]; };

// ---------------------------------------------------------------------------
// Kernel A: inside tests + candidate emission (warp-aggregated atomics).
// Axis-aligned quads: cross-product test == inclusive box test exactly.
// Warps never straddle rows (320 = 10*32) => quad y-mask is warp-uniform.
// ---------------------------------------------------------------------------
__global__ __launch_bounds__(256) void k_candidates(
    const float* __restrict__ confs, const float* __restrict__ rects, ImgKeys keys)
{
    const int b = blockIdx.y;
    const int p = blockIdx.x * 256 + threadIdx.x;
    __shared__ float qx0[TT], qy0[TT], qx1[TT], qy1[TT];
    if (threadIdx.x < TT) {
        const float* tr = rects + ((size_t)b * TT + threadIdx.x) * 12;
        qx0[threadIdx.x] = tr[4] * (float)WW;
        qy0[threadIdx.x] = tr[5] * (float)HH;
        qx1[threadIdx.x] = tr[8] * (float)WW;
        qy1[threadIdx.x] = tr[9] * (float)HH;
    }
    __syncthreads();

    const int y = p / WW;
    const int x = p - y * WW;
    const float px = (float)x + 0.5f;
    const float py = (float)y + 0.5f;
    const u32 cbits = __float_as_uint(confs[(size_t)b * HW + p]);
    const u32 kk0 = keys.k0[b], kk1 = keys.k1[b];
    const int lane = threadIdx.x & 31;

    u32 ymask = 0;                                  // warp-uniform
    #pragma unroll
    for (int t = 0; t < TT; t++)
        if (py >= qy0[t] && py <= qy1[t]) ymask |= (1u << t);

    while (ymask) {
        int t = __ffs(ymask) - 1;
        ymask &= ymask - 1;
        bool ins = (px >= qx0[t]) && (px <= qx1[t]);
        u32 m = __ballot_sync(0xffffffffu, ins);
        if (!m) continue;
        int base = 0;
        int leader = __ffs(m) - 1;
        if (lane == leader) base = atomicAdd(&g_cnt[b], __popc(m));
        base = __shfl_sync(0xffffffffu, base, leader);
        if (ins) {
            int pos = base + __popc(m & ((1u << lane) - 1u));
            if (pos < CAP) {
                u32 idx = (u32)(t * HW + p);
                u32 o0, o1;
                tf2x32(kk0, kk1, 0u, idx, o0, o1);  // partitionable random_bits
                u32 rb = (o0 ^ o1) >> 9;
                g_key[(size_t)b * CAP + (size_t)pos] =
                    make_ulonglong2(((u64)cbits << 21) | (u64)idx,
                                    ((u64)rb    << 21) | (u64)idx);
            }
        }
    }
}

// ---------------------------------------------------------------------------
// Kernel B1: full-chip parallel compaction of survivors.
// conf survivors: ck < Xc ; rand survivors: rk < Xr (pair kept for filter).
// Analytic thresholds target ~2048 survivors; window [K, SURV] can't miss
// statistically; k_select_sum has an exact fallback regardless.
// ---------------------------------------------------------------------------
__global__ __launch_bounds__(256) void k_compact()
{
    const int b = blockIdx.y;
    const int tid = threadIdx.x, lane = tid & 31;
    int C = g_cnt[b]; if (C > CAP) C = CAP;
    u64 Xc = MAXK, Xr = MAXK;
    if (C > 6144) {
        float q = 2048.0f / (float)C;
        Xc = ((u64)__float_as_uint(q)) << 21;
        u32 mant = (u32)(8388608.0f * q); if (mant < 1u) mant = 1u;
        Xr = ((u64)mant) << 21;
    }
    const ulonglong2* gp = g_key + (size_t)b * CAP;
    u64* sc = g_survc + b * SURV;
    ulonglong2* sr = g_survr + b * SURV;
    const int stride = 256 * gridDim.x;

    for (int i0 = blockIdx.x * 256; i0 < C; i0 += stride) {
        int i = i0 + tid;
        bool act = i < C;
        ulonglong2 kp = act ? gp[i] : make_ulonglong2(~0ull, ~0ull);
        bool okc = act && (kp.x < Xc);
        u32 m = __ballot_sync(0xffffffffu, okc);
        if (m) {
            int base = 0, leader = __ffs(m) - 1;
            if (lane == leader) base = atomicAdd(&g_nc[b], __popc(m));
            base = __shfl_sync(0xffffffffu, base, leader);
            if (okc) {
                int q2 = base + __popc(m & ((1u << lane) - 1u));
                if (q2 < SURV) sc[q2] = kp.x;
            }
        }
        bool okr = act && (kp.y < Xr);
        m = __ballot_sync(0xffffffffu, okr);
        if (m) {
            int base = 0, leader = __ffs(m) - 1;
            if (lane == leader) base = atomicAdd(&g_nr[b], __popc(m));
            base = __shfl_sync(0xffffffffu, base, leader);
            if (okr) {
                int q2 = base + __popc(m & ((1u << lane) - 1u));
                if (q2 < SURV) sr[q2] = kp;
            }
        }
    }
}

// ---------------------------------------------------------------------------
// Kernel B2 helpers
// ---------------------------------------------------------------------------

// Exact rank-R key (ascending) among n keys; 5 x 11-bit digit passes.
// mode 0: keys[] plain. mode 1: pairs[], key = .y, only where .x > F.
__device__ u64 sel_rank(const u64* __restrict__ keys,
                        const ulonglong2* __restrict__ pairs,
                        int mode, u64 F, int n, int R,
                        u32* hist, u32* wsum,
                        int* s_selw, int* s_rrem1, u64* s_prefix, int* s_rrem)
{
    const int tid = threadIdx.x, lane = tid & 31, wid = tid >> 5;
    u64 prefix = 0;
    #pragma unroll 1
    for (int shift = 44; shift >= 0; shift -= 11) {
        hist[tid] = 0; hist[tid + 1024] = 0;
        __syncthreads();
        u64 ph = prefix >> (shift + 11);
        for (int i = tid; i < n; i += 1024) {
            u64 k; bool ok;
            if (mode == 0) { k = keys[i]; ok = true; }
            else { ulonglong2 kp = pairs[i]; k = kp.y; ok = (kp.x > F); }
            if (ok && (k >> (shift + 11)) == ph)
                atomicAdd(&hist[(int)((k >> shift) & 2047u)], 1u);
        }
        __syncthreads();
        u32 s = hist[2 * tid] + hist[2 * tid + 1];
        u32 sc = s;
        #pragma unroll
        for (int o = 1; o < 32; o <<= 1) {
            u32 v = __shfl_up_sync(0xffffffffu, sc, o);
            if (lane >= o) sc += v;
        }
        if (lane == 31) wsum[wid] = sc;
        __syncthreads();
        if (wid == 0) {
            u32 wt = wsum[lane], wsc = wt;
            #pragma unroll
            for (int o = 1; o < 32; o <<= 1) {
                u32 v = __shfl_up_sync(0xffffffffu, wsc, o);
                if (lane >= o) wsc += v;
            }
            u32 excl = wsc - wt;
            bool hit = ((u32)R >= excl) && ((u32)R < wsc);
            u32 m = __ballot_sync(0xffffffffu, hit);
            if (m != 0u && lane == (__ffs(m) - 1)) { *s_selw = lane; *s_rrem1 = R - (int)excl; }
        }
        __syncthreads();
        if (wid == *s_selw) {
            int R1 = *s_rrem1;
            u32 excl = sc - s;
            bool hit = ((u32)R1 >= excl) && ((u32)R1 < sc);
            u32 m = __ballot_sync(0xffffffffu, hit);
            if (m != 0u && lane == (__ffs(m) - 1)) {
                int r2 = R1 - (int)excl;
                u32 c0 = hist[2 * tid];
                if ((u32)r2 < c0) { *s_prefix = prefix | ((u64)(2 * tid)     << shift); *s_rrem = r2; }
                else              { *s_prefix = prefix | ((u64)(2 * tid + 1) << shift); *s_rrem = r2 - (int)c0; }
            }
        }
        __syncthreads();
        prefix = *s_prefix;
        R = *s_rrem;
        __syncthreads();
    }
    return prefix;
}

// Count pairs with .x > F (padded ballot loop; warp-uniform trip count).
__device__ int blk_count_gt(const ulonglong2* __restrict__ pairs, int n, u64 F, int* s_cnt)
{
    const int tid = threadIdx.x, lane = tid & 31;
    __syncthreads();
    if (tid == 0) *s_cnt = 0;
    __syncthreads();
    for (int i0 = 0; i0 < n; i0 += 1024) {
        int i = i0 + tid;
        bool ok = (i < n) && (pairs[i].x > F);
        u32 m = __ballot_sync(0xffffffffu, ok);
        if (lane == 0 && m) atomicAdd(s_cnt, __popc(m));
    }
    __syncthreads();
    return *s_cnt;
}

// Fallback: exact rank-R key by 51-step MSB bit search over the FULL array.
// phase 0: key=.x, no filter. phase 1: key=.y, filter .x > F.
__device__ u64 bitsearch(const ulonglong2* __restrict__ gp, int C, int R,
                         int phase, u64 F, int* s_cnt)
{
    const int tid = threadIdx.x, lane = tid & 31;
    u64 prefix = 0;
    for (int bit = 50; bit >= 0; bit--) {
        u64 X = prefix | (1ull << bit);
        __syncthreads();
        if (tid == 0) *s_cnt = 0;
        __syncthreads();
        for (int i0 = 0; i0 < C; i0 += 1024) {
            int i = i0 + tid;
            bool ok = false;
            if (i < C) {
                ulonglong2 kp = gp[i];
                u64 k = phase ? kp.y : kp.x;
                ok = (phase ? (kp.x > F) : true) && (k < X);
            }
            u32 m = __ballot_sync(0xffffffffu, ok);
            if (lane == 0 && m) atomicAdd(s_cnt, __popc(m));
        }
        __syncthreads();
        if (R >= *s_cnt) prefix = X;
        __syncthreads();
    }
    return prefix;
}

__device__ __forceinline__ void accum(int idx, int b,
                                      const float* __restrict__ boxes,
                                      const float* __restrict__ rbase,
                                      const float* __restrict__ thetas,
                                      const float* __restrict__ tths,
                                      float& locs, float& oris)
{
    int t = idx / HW;
    int p = idx - t * HW;
    const float* pb = boxes + ((size_t)b * HW + p) * 4;
    const float* tr = rbase + t * 12;
    float tx0 = tr[0] * (float)WW, ty0 = tr[1] * (float)HH;
    float tx1 = tr[2] * (float)WW, ty1 = tr[3] * (float)HH;
    float px0 = pb[0], py0 = pb[1], px1 = pb[2], py1 = pb[3];
    float ix0 = fmaxf(px0, tx0), iy0 = fmaxf(py0, ty0);
    float ix1 = fminf(px1, tx1), iy1 = fminf(py1, ty1);
    float inter = fmaxf(ix1 - ix0, 0.f) * fmaxf(iy1 - iy0, 0.f);
    float ap = fmaxf(px1 - px0, 0.f) * fmaxf(py1 - py0, 0.f);
    float at = (tx1 - tx0) * (ty1 - ty0);
    float uni = ap + at - inter;
    locs += -logf((inter + 1.f) / (uni + 1.f));
    oris += 1.f - cosf(thetas[(size_t)b * HW + p] - tths[b * TT + t]);
}

// ---------------------------------------------------------------------------
// Kernel B2: selects on ~2k survivors + masked sums. One block per image.
// ---------------------------------------------------------------------------
__global__ __launch_bounds__(1024) void k_select_sum(
    const float* __restrict__ boxes, const float* __restrict__ rects,
    const float* __restrict__ thetas, const float* __restrict__ tths,
    float* __restrict__ out)
{
    __shared__ u32 hist[2048];     // also reused as reduction buffer
    __shared__ u32 wsum[32];
    __shared__ int s_selw, s_rrem1, s_rrem, s_cnt;
    __shared__ u64 s_prefix;

    const int b = blockIdx.x;
    const int tid = threadIdx.x;
    int C = g_cnt[b]; if (C > CAP) C = CAP;
    int nc = g_nc[b];
    int nr = g_nr[b];
    int K1 = C < KSEL ? C : KSEL;
    int C2 = C - K1;
    int K2 = C2 < KSEL ? C2 : KSEL;
    const u64* sc = g_survc + b * SURV;
    const ulonglong2* sr = g_survr + b * SURV;
    const ulonglong2* gp = g_key + (size_t)b * CAP;

    u64 Thard = 0, Trand = 0;
    bool fb = (nc > SURV) || (nr > SURV) || (nc < K1);
    if (C > 0) {
        if (!fb) {
            Thard = sel_rank(sc, (const ulonglong2*)0, 0, 0ull, nc, K1 - 1,
                             hist, wsum, &s_selw, &s_rrem1, &s_prefix, &s_rrem);
            if (C2 > 0) {
                int nrf = blk_count_gt(sr, nr, Thard, &s_cnt);
                if (nrf < K2) fb = true;
                else Trand = sel_rank((const u64*)0, sr, 1, Thard, nr, K2 - 1,
                                      hist, wsum, &s_selw, &s_rrem1, &s_prefix, &s_rrem);
            }
        }
        if (fb) {   // statistically unreachable; exact and deterministic
            Thard = bitsearch(gp, C, K1 - 1, 0, 0ull, &s_cnt);
            if (C2 > 0) Trand = bitsearch(gp, C, K2 - 1, 1, Thard, &s_cnt);
        }
    }

    // Masked sums (keys unique => exactly K1 + K2 selected).
    float locs = 0.f, oris = 0.f;
    const float* rbase = rects + (size_t)b * TT * 12;
    if (C > 0) {
        if (!fb) {
            for (int i = tid; i < nc; i += 1024) {
                u64 k = sc[i];
                if (k <= Thard) accum((int)(k & IDXM), b, boxes, rbase, thetas, tths, locs, oris);
            }
            if (C2 > 0) {
                for (int i = tid; i < nr; i += 1024) {
                    ulonglong2 kp = sr[i];
                    if (kp.x > Thard && kp.y <= Trand)
                        accum((int)(kp.y & IDXM), b, boxes, rbase, thetas, tths, locs, oris);
                }
            }
        } else {
            for (int i = tid; i < C; i += 1024) {
                ulonglong2 kp = gp[i];
                bool sel = (kp.x <= Thard) || (C2 > 0 && kp.x > Thard && kp.y <= Trand);
                if (sel) accum((int)(kp.x & IDXM), b, boxes, rbase, thetas, tths, locs, oris);
            }
        }
    }

    float* red  = (float*)hist;
    float* red2 = red + 1024;
    __syncthreads();
    red[tid] = locs; red2[tid] = oris;
    __syncthreads();
    for (int st = 512; st > 0; st >>= 1) {
        if (tid < st) { red[tid] += red[tid + st]; red2[tid] += red2[tid + st]; }
        __syncthreads();
    }
    if (tid == 0) {
        int n = K1 + K2; if (n < 1) n = 1;
        out[b] = (red[0] + 10.0f * red2[0]) / (float)n;
        g_cnt[b] = 0; g_nc[b] = 0; g_nr[b] = 0;   // reset for next graph replay
    }
}

// ---------------------------------------------------------------------------
extern "C" void kernel_launch(void* const* d_in, const int* in_sizes, int n_in,
                              void* d_out, int out_size)
{
    (void)in_sizes; (void)n_in; (void)out_size;
    const float* confs  = (const float*)d_in[0];   // (8,320,320,1)
    const float* boxes  = (const float*)d_in[1];   // (8,320,320,4)
    const float* rects  = (const float*)d_in[2];   // (8,16,12)
    const float* thetas = (const float*)d_in[3];   // (8,320,320,1)
    const float* tths   = (const float*)d_in[4];   // (8,16,1)
    float* out = (float*)d_out;                    // (8,)

    ImgKeys keys;
    for (int b = 0; b < BB; b++)
        tf2x32(0u, 42u, 0u, (u32)b, keys.k0[b], keys.k1[b]);

    k_candidates<<<dim3(HW / 256, BB), 256>>>(confs, rects, keys);
    k_compact<<<dim3(32, BB), 256>>>();
    k_select_sum<<<BB, 1024>>>(boxes, rects, thetas, tths, out);
}

// round 14
// speedup vs baseline: 1.0373x; 1.0373x over previous
#include <cuda_runtime.h>

typedef unsigned int u32;
typedef unsigned long long u64;

#define BB 8
#define HH 320
#define WW 320
#define TT 16
#define HW (HH*WW)            // 102400
#define CAP 163840            // max candidates/image <= 97*97*16 = 150544
#define KSEL 128
#define SURV 8192             // survivor capacity per image per phase
#define MAXK (1ull<<51)
#define IDXM 0x1FFFFFu

// Scratch (device globals; ~23 MB total).
//  ckey = (conf_bits << 21) | idx       (< 2^51)
//  rkey = (rand_mantissa23 << 21) | idx (< 2^44)
__device__ ulonglong2 g_key[(size_t)BB * CAP];
__device__ u64        g_survc[BB * SURV];      // conf survivors (ckey)
__device__ ulonglong2 g_survr[BB * SURV];      // rand survivors (ckey, rkey)
__device__ int g_cnt[BB], g_nc[BB], g_nr[BB];  // zero-init; reset at end of k_select_sum

// ---------------------------------------------------------------------------
// Threefry-2x32 (JAX rotation schedule), host + device.
// ---------------------------------------------------------------------------
__host__ __device__ __forceinline__ void tf2x32(u32 k0, u32 k1, u32 x0, u32 x1,
                                                u32 &o0, u32 &o1)
{
    u32 ks2 = k0 ^ k1 ^ 0x1BD11BDAu;
    x0 += k0; x1 += k1;
#define ROTL32(v,d) (((v)<<(d))|((v)>>(32-(d))))
#define TFR(r) { x0 += x1; x1 = ROTL32(x1,(r)); x1 ^= x0; }
    TFR(13) TFR(15) TFR(26) TFR(6)  x0 += k1;  x1 += ks2 + 1u;
    TFR(17) TFR(29) TFR(16) TFR(24) x0 += ks2; x1 += k0 + 2u;
    TFR(13) TFR(15) TFR(26) TFR(6)  x0 += k0;  x1 += k1 + 3u;
    TFR(17) TFR(29) TFR(16) TFR(24) x0 += k1;  x1 += ks2 + 4u;
    TFR(13) TFR(15) TFR(26) TFR(6)  x0 += ks2; x1 += k0 + 5u;
#undef TFR
#undef ROTL32
    o0 = x0; o1 = x1;
}

struct ImgKeys { u32 k0[BB]; u32 k1[BB]; };

// ---------------------------------------------------------------------------
// Kernel A: inside tests + candidate emission (warp-aggregated atomics).
// Axis-aligned quads: cross-product test == inclusive box test exactly.
// Warps never straddle rows (320 = 10*32) => quad y-mask is warp-uniform.
// ---------------------------------------------------------------------------
__global__ __launch_bounds__(256) void k_candidates(
    const float* __restrict__ confs, const float* __restrict__ rects, ImgKeys keys)
{
    const int b = blockIdx.y;
    const int p = blockIdx.x * 256 + threadIdx.x;
    __shared__ float qx0[TT], qy0[TT], qx1[TT], qy1[TT];
    if (threadIdx.x < TT) {
        const float* tr = rects + ((size_t)b * TT + threadIdx.x) * 12;
        qx0[threadIdx.x] = tr[4] * (float)WW;
        qy0[threadIdx.x] = tr[5] * (float)HH;
        qx1[threadIdx.x] = tr[8] * (float)WW;
        qy1[threadIdx.x] = tr[9] * (float)HH;
    }
    __syncthreads();

    const int y = p / WW;
    const int x = p - y * WW;
    const float px = (float)x + 0.5f;
    const float py = (float)y + 0.5f;
    const u32 cbits = __float_as_uint(confs[(size_t)b * HW + p]);
    const u32 kk0 = keys.k0[b], kk1 = keys.k1[b];
    const int lane = threadIdx.x & 31;

    u32 ymask = 0;                                  // warp-uniform
    #pragma unroll
    for (int t = 0; t < TT; t++)
        if (py >= qy0[t] && py <= qy1[t]) ymask |= (1u << t);

    while (ymask) {
        int t = __ffs(ymask) - 1;
        ymask &= ymask - 1;
        bool ins = (px >= qx0[t]) && (px <= qx1[t]);
        u32 m = __ballot_sync(0xffffffffu, ins);
        if (!m) continue;
        int base = 0;
        int leader = __ffs(m) - 1;
        if (lane == leader) base = atomicAdd(&g_cnt[b], __popc(m));
        base = __shfl_sync(0xffffffffu, base, leader);
        if (ins) {
            int pos = base + __popc(m & ((1u << lane) - 1u));
            if (pos < CAP) {
                u32 idx = (u32)(t * HW + p);
                u32 o0, o1;
                tf2x32(kk0, kk1, 0u, idx, o0, o1);  // partitionable random_bits
                u32 rb = (o0 ^ o1) >> 9;
                g_key[(size_t)b * CAP + (size_t)pos] =
                    make_ulonglong2(((u64)cbits << 21) | (u64)idx,
                                    ((u64)rb    << 21) | (u64)idx);
            }
        }
    }
}

// ---------------------------------------------------------------------------
// Kernel B1: full-chip parallel compaction of survivors.
// conf survivors: ck < Xc ; rand survivors: rk < Xr (pair kept for filter).
// Analytic thresholds target ~2048 survivors; window [K, SURV] can't miss
// statistically; k_select_sum has an exact fallback regardless.
// ---------------------------------------------------------------------------
__global__ __launch_bounds__(256) void k_compact()
{
    const int b = blockIdx.y;
    const int tid = threadIdx.x, lane = tid & 31;
    int C = g_cnt[b]; if (C > CAP) C = CAP;
    u64 Xc = MAXK, Xr = MAXK;
    if (C > 6144) {
        float q = 2048.0f / (float)C;
        Xc = ((u64)__float_as_uint(q)) << 21;
        u32 mant = (u32)(8388608.0f * q); if (mant < 1u) mant = 1u;
        Xr = ((u64)mant) << 21;
    }
    const ulonglong2* gp = g_key + (size_t)b * CAP;
    u64* sc = g_survc + b * SURV;
    ulonglong2* sr = g_survr + b * SURV;
    const int stride = 256 * gridDim.x;

    for (int i0 = blockIdx.x * 256; i0 < C; i0 += stride) {
        int i = i0 + tid;
        bool act = i < C;
        ulonglong2 kp = act ? gp[i] : make_ulonglong2(~0ull, ~0ull);
        bool okc = act && (kp.x < Xc);
        u32 m = __ballot_sync(0xffffffffu, okc);
        if (m) {
            int base = 0, leader = __ffs(m) - 1;
            if (lane == leader) base = atomicAdd(&g_nc[b], __popc(m));
            base = __shfl_sync(0xffffffffu, base, leader);
            if (okc) {
                int q2 = base + __popc(m & ((1u << lane) - 1u));
                if (q2 < SURV) sc[q2] = kp.x;
            }
        }
        bool okr = act && (kp.y < Xr);
        m = __ballot_sync(0xffffffffu, okr);
        if (m) {
            int base = 0, leader = __ffs(m) - 1;
            if (lane == leader) base = atomicAdd(&g_nr[b], __popc(m));
            base = __shfl_sync(0xffffffffu, base, leader);
            if (okr) {
                int q2 = base + __popc(m & ((1u << lane) - 1u));
                if (q2 < SURV) sr[q2] = kp;
            }
        }
    }
}

// ---------------------------------------------------------------------------
// Kernel B2 helpers
// ---------------------------------------------------------------------------

// Exact rank-R key (ascending) among n keys; 5 x 11-bit digit passes.
// mode 0: keys[] plain. mode 1: pairs[], key = .y, only where .x > F.
__device__ u64 sel_rank(const u64* __restrict__ keys,
                        const ulonglong2* __restrict__ pairs,
                        int mode, u64 F, int n, int R,
                        u32* hist, u32* wsum,
                        int* s_selw, int* s_rrem1, u64* s_prefix, int* s_rrem)
{
    const int tid = threadIdx.x, lane = tid & 31, wid = tid >> 5;
    u64 prefix = 0;
    #pragma unroll 1
    for (int shift = 44; shift >= 0; shift -= 11) {
        hist[tid] = 0; hist[tid + 1024] = 0;
        __syncthreads();
        u64 ph = prefix >> (shift + 11);
        for (int i = tid; i < n; i += 1024) {
            u64 k; bool ok;
            if (mode == 0) { k = keys[i]; ok = true; }
            else { ulonglong2 kp = pairs[i]; k = kp.y; ok = (kp.x > F); }
            if (ok && (k >> (shift + 11)) == ph)
                atomicAdd(&hist[(int)((k >> shift) & 2047u)], 1u);
        }
        __syncthreads();
        u32 s = hist[2 * tid] + hist[2 * tid + 1];
        u32 sc = s;
        #pragma unroll
        for (int o = 1; o < 32; o <<= 1) {
            u32 v = __shfl_up_sync(0xffffffffu, sc, o);
            if (lane >= o) sc += v;
        }
        if (lane == 31) wsum[wid] = sc;
        __syncthreads();
        if (wid == 0) {
            u32 wt = wsum[lane], wsc = wt;
            #pragma unroll
            for (int o = 1; o < 32; o <<= 1) {
                u32 v = __shfl_up_sync(0xffffffffu, wsc, o);
                if (lane >= o) wsc += v;
            }
            u32 excl = wsc - wt;
            bool hit = ((u32)R >= excl) && ((u32)R < wsc);
            u32 m = __ballot_sync(0xffffffffu, hit);
            if (m != 0u && lane == (__ffs(m) - 1)) { *s_selw = lane; *s_rrem1 = R - (int)excl; }
        }
        __syncthreads();
        if (wid == *s_selw) {
            int R1 = *s_rrem1;
            u32 excl = sc - s;
            bool hit = ((u32)R1 >= excl) && ((u32)R1 < sc);
            u32 m = __ballot_sync(0xffffffffu, hit);
            if (m != 0u && lane == (__ffs(m) - 1)) {
                int r2 = R1 - (int)excl;
                u32 c0 = hist[2 * tid];
                if ((u32)r2 < c0) { *s_prefix = prefix | ((u64)(2 * tid)     << shift); *s_rrem = r2; }
                else              { *s_prefix = prefix | ((u64)(2 * tid + 1) << shift); *s_rrem = r2 - (int)c0; }
            }
        }
        __syncthreads();
        prefix = *s_prefix;
        R = *s_rrem;
        __syncthreads();
    }
    return prefix;
}

// Count pairs with .x > F (padded ballot loop; warp-uniform trip count).
__device__ int blk_count_gt(const ulonglong2* __restrict__ pairs, int n, u64 F, int* s_cnt)
{
    const int tid = threadIdx.x, lane = tid & 31;
    __syncthreads();
    if (tid == 0) *s_cnt = 0;
    __syncthreads();
    for (int i0 = 0; i0 < n; i0 += 1024) {
        int i = i0 + tid;
        bool ok = (i < n) && (pairs[i].x > F);
        u32 m = __ballot_sync(0xffffffffu, ok);
        if (lane == 0 && m) atomicAdd(s_cnt, __popc(m));
    }
    __syncthreads();
    return *s_cnt;
}

// Fallback: exact rank-R key by 51-step MSB bit search over the FULL array.
// phase 0: key=.x, no filter. phase 1: key=.y, filter .x > F.
__device__ u64 bitsearch(const ulonglong2* __restrict__ gp, int C, int R,
                         int phase, u64 F, int* s_cnt)
{
    const int tid = threadIdx.x, lane = tid & 31;
    u64 prefix = 0;
    for (int bit = 50; bit >= 0; bit--) {
        u64 X = prefix | (1ull << bit);
        __syncthreads();
        if (tid == 0) *s_cnt = 0;
        __syncthreads();
        for (int i0 = 0; i0 < C; i0 += 1024) {
            int i = i0 + tid;
            bool ok = false;
            if (i < C) {
                ulonglong2 kp = gp[i];
                u64 k = phase ? kp.y : kp.x;
                ok = (phase ? (kp.x > F) : true) && (k < X);
            }
            u32 m = __ballot_sync(0xffffffffu, ok);
            if (lane == 0 && m) atomicAdd(s_cnt, __popc(m));
        }
        __syncthreads();
        if (R >= *s_cnt) prefix = X;
        __syncthreads();
    }
    return prefix;
}

__device__ __forceinline__ void accum(int idx, int b,
                                      const float* __restrict__ boxes,
                                      const float* __restrict__ rbase,
                                      const float* __restrict__ thetas,
                                      const float* __restrict__ tths,
                                      float& locs, float& oris)
{
    int t = idx / HW;
    int p = idx - t * HW;
    const float* pb = boxes + ((size_t)b * HW + p) * 4;
    const float* tr = rbase + t * 12;
    float tx0 = tr[0] * (float)WW, ty0 = tr[1] * (float)HH;
    float tx1 = tr[2] * (float)WW, ty1 = tr[3] * (float)HH;
    float px0 = pb[0], py0 = pb[1], px1 = pb[2], py1 = pb[3];
    float ix0 = fmaxf(px0, tx0), iy0 = fmaxf(py0, ty0);
    float ix1 = fminf(px1, tx1), iy1 = fminf(py1, ty1);
    float inter = fmaxf(ix1 - ix0, 0.f) * fmaxf(iy1 - iy0, 0.f);
    float ap = fmaxf(px1 - px0, 0.f) * fmaxf(py1 - py0, 0.f);
    float at = (tx1 - tx0) * (ty1 - ty0);
    float uni = ap + at - inter;
    locs += -logf((inter + 1.f) / (uni + 1.f));
    oris += 1.f - cosf(thetas[(size_t)b * HW + p] - tths[b * TT + t]);
}

// ---------------------------------------------------------------------------
// Kernel B2: selects on ~2k survivors + masked sums. One block per image.
// ---------------------------------------------------------------------------
__global__ __launch_bounds__(1024) void k_select_sum(
    const float* __restrict__ boxes, const float* __restrict__ rects,
    const float* __restrict__ thetas, const float* __restrict__ tths,
    float* __restrict__ out)
{
    __shared__ u32 hist[2048];     // also reused as reduction buffer
    __shared__ u32 wsum[32];
    __shared__ int s_selw, s_rrem1, s_rrem, s_cnt;
    __shared__ u64 s_prefix;

    const int b = blockIdx.x;
    const int tid = threadIdx.x;
    int C = g_cnt[b]; if (C > CAP) C = CAP;
    int nc = g_nc[b];
    int nr = g_nr[b];
    int K1 = C < KSEL ? C : KSEL;
    int C2 = C - K1;
    int K2 = C2 < KSEL ? C2 : KSEL;
    const u64* sc = g_survc + b * SURV;
    const ulonglong2* sr = g_survr + b * SURV;
    const ulonglong2* gp = g_key + (size_t)b * CAP;

    u64 Thard = 0, Trand = 0;
    bool fb = (nc > SURV) || (nr > SURV) || (nc < K1);
    if (C > 0) {
        if (!fb) {
            Thard = sel_rank(sc, (const ulonglong2*)0, 0, 0ull, nc, K1 - 1,
                             hist, wsum, &s_selw, &s_rrem1, &s_prefix, &s_rrem);
            if (C2 > 0) {
                int nrf = blk_count_gt(sr, nr, Thard, &s_cnt);
                if (nrf < K2) fb = true;
                else Trand = sel_rank((const u64*)0, sr, 1, Thard, nr, K2 - 1,
                                      hist, wsum, &s_selw, &s_rrem1, &s_prefix, &s_rrem);
            }
        }
        if (fb) {   // statistically unreachable; exact and deterministic
            Thard = bitsearch(gp, C, K1 - 1, 0, 0ull, &s_cnt);
            if (C2 > 0) Trand = bitsearch(gp, C, K2 - 1, 1, Thard, &s_cnt);
        }
    }

    // Masked sums (keys unique => exactly K1 + K2 selected).
    float locs = 0.f, oris = 0.f;
    const float* rbase = rects + (size_t)b * TT * 12;
    if (C > 0) {
        if (!fb) {
            for (int i = tid; i < nc; i += 1024) {
                u64 k = sc[i];
                if (k <= Thard) accum((int)(k & IDXM), b, boxes, rbase, thetas, tths, locs, oris);
            }
            if (C2 > 0) {
                for (int i = tid; i < nr; i += 1024) {
                    ulonglong2 kp = sr[i];
                    if (kp.x > Thard && kp.y <= Trand)
                        accum((int)(kp.y & IDXM), b, boxes, rbase, thetas, tths, locs, oris);
                }
            }
        } else {
            for (int i = tid; i < C; i += 1024) {
                ulonglong2 kp = gp[i];
                bool sel = (kp.x <= Thard) || (C2 > 0 && kp.x > Thard && kp.y <= Trand);
                if (sel) accum((int)(kp.x & IDXM), b, boxes, rbase, thetas, tths, locs, oris);
            }
        }
    }

    float* red  = (float*)hist;
    float* red2 = red + 1024;
    __syncthreads();
    red[tid] = locs; red2[tid] = oris;
    __syncthreads();
    for (int st = 512; st > 0; st >>= 1) {
        if (tid < st) { red[tid] += red[tid + st]; red2[tid] += red2[tid + st]; }
        __syncthreads();
    }
    if (tid == 0) {
        int n = K1 + K2; if (n < 1) n = 1;
        out[b] = (red[0] + 10.0f * red2[0]) / (float)n;
        g_cnt[b] = 0; g_nc[b] = 0; g_nr[b] = 0;   // reset for next graph replay
    }
}

// ---------------------------------------------------------------------------
extern "C" void kernel_launch(void* const* d_in, const int* in_sizes, int n_in,
                              void* d_out, int out_size)
{
    (void)in_sizes; (void)n_in; (void)out_size;
    const float* confs  = (const float*)d_in[0];   // (8,320,320,1)
    const float* boxes  = (const float*)d_in[1];   // (8,320,320,4)
    const float* rects  = (const float*)d_in[2];   // (8,16,12)
    const float* thetas = (const float*)d_in[3];   // (8,320,320,1)
    const float* tths   = (const float*)d_in[4];   // (8,16,1)
    float* out = (float*)d_out;                    // (8,)

    ImgKeys keys;
    for (int b = 0; b < BB; b++)
        tf2x32(0u, 42u, 0u, (u32)b, keys.k0[b], keys.k1[b]);

    k_candidates<<<dim3(HW / 256, BB), 256>>>(confs, rects, keys);
    k_compact<<<dim3(32, BB), 256>>>();
    k_select_sum<<<BB, 1024>>>(boxes, rects, thetas, tths, out);
}

// round 15
// speedup vs baseline: 1.0481x; 1.0104x over previous
#include <cuda_runtime.h>

typedef unsigned int u32;
typedef unsigned long long u64;

#define BB 8
#define HH 320
#define WW 320
#define TT 16
#define HW (HH*WW)            // 102400
#define CAP 163840            // max candidates/image <= 97*97*16 = 150544
#define KSEL 128
#define SURV 8192             // survivor capacity per image per phase
#define MAXK (1ull<<51)
#define IDXM 0x1FFFFFu

// Scratch (device globals; ~23 MB total).
//  ckey = (conf_bits << 21) | idx       (< 2^51)
//  rkey = (rand_mantissa23 << 21) | idx (< 2^44)
__device__ ulonglong2 g_key[(size_t)BB * CAP];
__device__ u64        g_survc[BB * SURV];      // conf survivors (ckey)
__device__ ulonglong2 g_survr[BB * SURV];      // rand survivors (ckey, rkey)
__device__ int g_cnt[BB], g_nc[BB], g_nr[BB];  // zero-init; reset at end of k_select_sum

// ---------------------------------------------------------------------------
// Threefry-2x32 (JAX rotation schedule), host + device.
// ---------------------------------------------------------------------------
__host__ __device__ __forceinline__ void tf2x32(u32 k0, u32 k1, u32 x0, u32 x1,
                                                u32 &o0, u32 &o1)
{
    u32 ks2 = k0 ^ k1 ^ 0x1BD11BDAu;
    x0 += k0; x1 += k1;
#define ROTL32(v,d) (((v)<<(d))|((v)>>(32-(d))))
#define TFR(r) { x0 += x1; x1 = ROTL32(x1,(r)); x1 ^= x0; }
    TFR(13) TFR(15) TFR(26) TFR(6)  x0 += k1;  x1 += ks2 + 1u;
    TFR(17) TFR(29) TFR(16) TFR(24) x0 += ks2; x1 += k0 + 2u;
    TFR(13) TFR(15) TFR(26) TFR(6)  x0 += k0;  x1 += k1 + 3u;
    TFR(17) TFR(29) TFR(16) TFR(24) x0 += k1;  x1 += ks2 + 4u;
    TFR(13) TFR(15) TFR(26) TFR(6)  x0 += ks2; x1 += k0 + 5u;
#undef TFR
#undef ROTL32
    o0 = x0; o1 = x1;
}

struct ImgKeys { u32 k0[BB]; u32 k1[BB]; };

// ---------------------------------------------------------------------------
// Kernel A: inside tests + candidate emission (warp-aggregated atomics).
// Axis-aligned quads: cross-product test == inclusive box test exactly.
// Warps never straddle rows (320 = 10*32) => quad y-mask is warp-uniform.
// ---------------------------------------------------------------------------
__global__ __launch_bounds__(256) void k_candidates(
    const float* __restrict__ confs, const float* __restrict__ rects, ImgKeys keys)
{
    const int b = blockIdx.y;
    const int p = blockIdx.x * 256 + threadIdx.x;
    __shared__ float qx0[TT], qy0[TT], qx1[TT], qy1[TT];
    if (threadIdx.x < TT) {
        const float* tr = rects + ((size_t)b * TT + threadIdx.x) * 12;
        qx0[threadIdx.x] = tr[4] * (float)WW;
        qy0[threadIdx.x] = tr[5] * (float)HH;
        qx1[threadIdx.x] = tr[8] * (float)WW;
        qy1[threadIdx.x] = tr[9] * (float)HH;
    }
    __syncthreads();

    const int y = p / WW;
    const int x = p - y * WW;
    const float px = (float)x + 0.5f;
    const float py = (float)y + 0.5f;
    const u32 cbits = __float_as_uint(confs[(size_t)b * HW + p]);
    const u32 kk0 = keys.k0[b], kk1 = keys.k1[b];
    const int lane = threadIdx.x & 31;

    u32 ymask = 0;                                  // warp-uniform
    #pragma unroll
    for (int t = 0; t < TT; t++)
        if (py >= qy0[t] && py <= qy1[t]) ymask |= (1u << t);

    while (ymask) {
        int t = __ffs(ymask) - 1;
        ymask &= ymask - 1;
        bool ins = (px >= qx0[t]) && (px <= qx1[t]);
        u32 m = __ballot_sync(0xffffffffu, ins);
        if (!m) continue;
        int base = 0;
        int leader = __ffs(m) - 1;
        if (lane == leader) base = atomicAdd(&g_cnt[b], __popc(m));
        base = __shfl_sync(0xffffffffu, base, leader);
        if (ins) {
            int pos = base + __popc(m & ((1u << lane) - 1u));
            if (pos < CAP) {
                u32 idx = (u32)(t * HW + p);
                u32 o0, o1;
                tf2x32(kk0, kk1, 0u, idx, o0, o1);  // partitionable random_bits
                u32 rb = (o0 ^ o1) >> 9;
                g_key[(size_t)b * CAP + (size_t)pos] =
                    make_ulonglong2(((u64)cbits << 21) | (u64)idx,
                                    ((u64)rb    << 21) | (u64)idx);
            }
        }
    }
}

// ---------------------------------------------------------------------------
// Kernel B1: full-chip parallel compaction of survivors.
// conf survivors: ck < Xc ; rand survivors: rk < Xr (pair kept for filter).
// Analytic thresholds target ~2048 survivors; window [K, SURV] can't miss
// statistically; k_select_sum has an exact fallback regardless.
// ---------------------------------------------------------------------------
__global__ __launch_bounds__(256) void k_compact()
{
    const int b = blockIdx.y;
    const int tid = threadIdx.x, lane = tid & 31;
    int C = g_cnt[b]; if (C > CAP) C = CAP;
    u64 Xc = MAXK, Xr = MAXK;
    if (C > 6144) {
        float q = 2048.0f / (float)C;
        Xc = ((u64)__float_as_uint(q)) << 21;
        u32 mant = (u32)(8388608.0f * q); if (mant < 1u) mant = 1u;
        Xr = ((u64)mant) << 21;
    }
    const ulonglong2* gp = g_key + (size_t)b * CAP;
    u64* sc = g_survc + b * SURV;
    ulonglong2* sr = g_survr + b * SURV;
    const int stride = 256 * gridDim.x;

    for (int i0 = blockIdx.x * 256; i0 < C; i0 += stride) {
        int i = i0 + tid;
        bool act = i < C;
        ulonglong2 kp = act ? gp[i] : make_ulonglong2(~0ull, ~0ull);
        bool okc = act && (kp.x < Xc);
        u32 m = __ballot_sync(0xffffffffu, okc);
        if (m) {
            int base = 0, leader = __ffs(m) - 1;
            if (lane == leader) base = atomicAdd(&g_nc[b], __popc(m));
            base = __shfl_sync(0xffffffffu, base, leader);
            if (okc) {
                int q2 = base + __popc(m & ((1u << lane) - 1u));
                if (q2 < SURV) sc[q2] = kp.x;
            }
        }
        bool okr = act && (kp.y < Xr);
        m = __ballot_sync(0xffffffffu, okr);
        if (m) {
            int base = 0, leader = __ffs(m) - 1;
            if (lane == leader) base = atomicAdd(&g_nr[b], __popc(m));
            base = __shfl_sync(0xffffffffu, base, leader);
            if (okr) {
                int q2 = base + __popc(m & ((1u << lane) - 1u));
                if (q2 < SURV) sr[q2] = kp;
            }
        }
    }
}

// ---------------------------------------------------------------------------
// Kernel B2 helpers
// ---------------------------------------------------------------------------

// Exact rank-R key (ascending) among n keys; 5 x 11-bit digit passes.
// mode 0: keys[] plain. mode 1: pairs[], key = .y, only where .x > F.
__device__ u64 sel_rank(const u64* __restrict__ keys,
                        const ulonglong2* __restrict__ pairs,
                        int mode, u64 F, int n, int R,
                        u32* hist, u32* wsum,
                        int* s_selw, int* s_rrem1, u64* s_prefix, int* s_rrem)
{
    const int tid = threadIdx.x, lane = tid & 31, wid = tid >> 5;
    u64 prefix = 0;
    #pragma unroll 1
    for (int shift = 44; shift >= 0; shift -= 11) {
        hist[tid] = 0; hist[tid + 1024] = 0;
        __syncthreads();
        u64 ph = prefix >> (shift + 11);
        for (int i = tid; i < n; i += 1024) {
            u64 k; bool ok;
            if (mode == 0) { k = keys[i]; ok = true; }
            else { ulonglong2 kp = pairs[i]; k = kp.y; ok = (kp.x > F); }
            if (ok && (k >> (shift + 11)) == ph)
                atomicAdd(&hist[(int)((k >> shift) & 2047u)], 1u);
        }
        __syncthreads();
        u32 s = hist[2 * tid] + hist[2 * tid + 1];
        u32 sc = s;
        #pragma unroll
        for (int o = 1; o < 32; o <<= 1) {
            u32 v = __shfl_up_sync(0xffffffffu, sc, o);
            if (lane >= o) sc += v;
        }
        if (lane == 31) wsum[wid] = sc;
        __syncthreads();
        if (wid == 0) {
            u32 wt = wsum[lane], wsc = wt;
            #pragma unroll
            for (int o = 1; o < 32; o <<= 1) {
                u32 v = __shfl_up_sync(0xffffffffu, wsc, o);
                if (lane >= o) wsc += v;
            }
            u32 excl = wsc - wt;
            bool hit = ((u32)R >= excl) && ((u32)R < wsc);
            u32 m = __ballot_sync(0xffffffffu, hit);
            if (m != 0u && lane == (__ffs(m) - 1)) { *s_selw = lane; *s_rrem1 = R - (int)excl; }
        }
        __syncthreads();
        if (wid == *s_selw) {
            int R1 = *s_rrem1;
            u32 excl = sc - s;
            bool hit = ((u32)R1 >= excl) && ((u32)R1 < sc);
            u32 m = __ballot_sync(0xffffffffu, hit);
            if (m != 0u && lane == (__ffs(m) - 1)) {
                int r2 = R1 - (int)excl;
                u32 c0 = hist[2 * tid];
                if ((u32)r2 < c0) { *s_prefix = prefix | ((u64)(2 * tid)     << shift); *s_rrem = r2; }
                else              { *s_prefix = prefix | ((u64)(2 * tid + 1) << shift); *s_rrem = r2 - (int)c0; }
            }
        }
        __syncthreads();
        prefix = *s_prefix;
        R = *s_rrem;
        __syncthreads();
    }
    return prefix;
}

// Count pairs with .x > F (padded ballot loop; warp-uniform trip count).
__device__ int blk_count_gt(const ulonglong2* __restrict__ pairs, int n, u64 F, int* s_cnt)
{
    const int tid = threadIdx.x, lane = tid & 31;
    __syncthreads();
    if (tid == 0) *s_cnt = 0;
    __syncthreads();
    for (int i0 = 0; i0 < n; i0 += 1024) {
        int i = i0 + tid;
        bool ok = (i < n) && (pairs[i].x > F);
        u32 m = __ballot_sync(0xffffffffu, ok);
        if (lane == 0 && m) atomicAdd(s_cnt, __popc(m));
    }
    __syncthreads();
    return *s_cnt;
}

// Fallback: exact rank-R key by 51-step MSB bit search over the FULL array.
// phase 0: key=.x, no filter. phase 1: key=.y, filter .x > F.
__device__ u64 bitsearch(const ulonglong2* __restrict__ gp, int C, int R,
                         int phase, u64 F, int* s_cnt)
{
    const int tid = threadIdx.x, lane = tid & 31;
    u64 prefix = 0;
    for (int bit = 50; bit >= 0; bit--) {
        u64 X = prefix | (1ull << bit);
        __syncthreads();
        if (tid == 0) *s_cnt = 0;
        __syncthreads();
        for (int i0 = 0; i0 < C; i0 += 1024) {
            int i = i0 + tid;
            bool ok = false;
            if (i < C) {
                ulonglong2 kp = gp[i];
                u64 k = phase ? kp.y : kp.x;
                ok = (phase ? (kp.x > F) : true) && (k < X);
            }
            u32 m = __ballot_sync(0xffffffffu, ok);
            if (lane == 0 && m) atomicAdd(s_cnt, __popc(m));
        }
        __syncthreads();
        if (R >= *s_cnt) prefix = X;
        __syncthreads();
    }
    return prefix;
}

__device__ __forceinline__ void accum(int idx, int b,
                                      const float* __restrict__ boxes,
                                      const float* __restrict__ rbase,
                                      const float* __restrict__ thetas,
                                      const float* __restrict__ tths,
                                      float& locs, float& oris)
{
    int t = idx / HW;
    int p = idx - t * HW;
    const float* pb = boxes + ((size_t)b * HW + p) * 4;
    const float* tr = rbase + t * 12;
    float tx0 = tr[0] * (float)WW, ty0 = tr[1] * (float)HH;
    float tx1 = tr[2] * (float)WW, ty1 = tr[3] * (float)HH;
    float px0 = pb[0], py0 = pb[1], px1 = pb[2], py1 = pb[3];
    float ix0 = fmaxf(px0, tx0), iy0 = fmaxf(py0, ty0);
    float ix1 = fminf(px1, tx1), iy1 = fminf(py1, ty1);
    float inter = fmaxf(ix1 - ix0, 0.f) * fmaxf(iy1 - iy0, 0.f);
    float ap = fmaxf(px1 - px0, 0.f) * fmaxf(py1 - py0, 0.f);
    float at = (tx1 - tx0) * (ty1 - ty0);
    float uni = ap + at - inter;
    locs += -logf((inter + 1.f) / (uni + 1.f));
    oris += 1.f - cosf(thetas[(size_t)b * HW + p] - tths[b * TT + t]);
}

// ---------------------------------------------------------------------------
// Kernel B2: selects on ~2k survivors + masked sums. One block per image.
// ---------------------------------------------------------------------------
__global__ __launch_bounds__(1024) void k_select_sum(
    const float* __restrict__ boxes, const float* __restrict__ rects,
    const float* __restrict__ thetas, const float* __restrict__ tths,
    float* __restrict__ out)
{
    __shared__ u32 hist[2048];     // also reused as reduction buffer
    __shared__ u32 wsum[32];
    __shared__ int s_selw, s_rrem1, s_rrem, s_cnt;
    __shared__ u64 s_prefix;

    const int b = blockIdx.x;
    const int tid = threadIdx.x;
    int C = g_cnt[b]; if (C > CAP) C = CAP;
    int nc = g_nc[b];
    int nr = g_nr[b];
    int K1 = C < KSEL ? C : KSEL;
    int C2 = C - K1;
    int K2 = C2 < KSEL ? C2 : KSEL;
    const u64* sc = g_survc + b * SURV;
    const ulonglong2* sr = g_survr + b * SURV;
    const ulonglong2* gp = g_key + (size_t)b * CAP;

    u64 Thard = 0, Trand = 0;
    bool fb = (nc > SURV) || (nr > SURV) || (nc < K1);
    if (C > 0) {
        if (!fb) {
            Thard = sel_rank(sc, (const ulonglong2*)0, 0, 0ull, nc, K1 - 1,
                             hist, wsum, &s_selw, &s_rrem1, &s_prefix, &s_rrem);
            if (C2 > 0) {
                int nrf = blk_count_gt(sr, nr, Thard, &s_cnt);
                if (nrf < K2) fb = true;
                else Trand = sel_rank((const u64*)0, sr, 1, Thard, nr, K2 - 1,
                                      hist, wsum, &s_selw, &s_rrem1, &s_prefix, &s_rrem);
            }
        }
        if (fb) {   // statistically unreachable; exact and deterministic
            Thard = bitsearch(gp, C, K1 - 1, 0, 0ull, &s_cnt);
            if (C2 > 0) Trand = bitsearch(gp, C, K2 - 1, 1, Thard, &s_cnt);
        }
    }

    // Masked sums (keys unique => exactly K1 + K2 selected).
    float locs = 0.f, oris = 0.f;
    const float* rbase = rects + (size_t)b * TT * 12;
    if (C > 0) {
        if (!fb) {
            for (int i = tid; i < nc; i += 1024) {
                u64 k = sc[i];
                if (k <= Thard) accum((int)(k & IDXM), b, boxes, rbase, thetas, tths, locs, oris);
            }
            if (C2 > 0) {
                for (int i = tid; i < nr; i += 1024) {
                    ulonglong2 kp = sr[i];
                    if (kp.x > Thard && kp.y <= Trand)
                        accum((int)(kp.y & IDXM), b, boxes, rbase, thetas, tths, locs, oris);
                }
            }
        } else {
            for (int i = tid; i < C; i += 1024) {
                ulonglong2 kp = gp[i];
                bool sel = (kp.x <= Thard) || (C2 > 0 && kp.x > Thard && kp.y <= Trand);
                if (sel) accum((int)(kp.x & IDXM), b, boxes, rbase, thetas, tths, locs, oris);
            }
        }
    }

    float* red  = (float*)hist;
    float* red2 = red + 1024;
    __syncthreads();
    red[tid] = locs; red2[tid] = oris;
    __syncthreads();
    for (int st = 512; st > 0; st >>= 1) {
        if (tid < st) { red[tid] += red[tid + st]; red2[tid] += red2[tid + st]; }
        __syncthreads();
    }
    if (tid == 0) {
        int n = K1 + K2; if (n < 1) n = 1;
        out[b] = (red[0] + 10.0f * red2[0]) / (float)n;
        g_cnt[b] = 0; g_nc[b] = 0; g_nr[b] = 0;   // reset for next graph replay
    }
}

// ---------------------------------------------------------------------------
extern "C" void kernel_launch(void* const* d_in, const int* in_sizes, int n_in,
                              void* d_out, int out_size)
{
    (void)in_sizes; (void)n_in; (void)out_size;
    const float* confs  = (const float*)d_in[0];   // (8,320,320,1)
    const float* boxes  = (const float*)d_in[1];   // (8,320,320,4)
    const float* rects  = (const float*)d_in[2];   // (8,16,12)
    const float* thetas = (const float*)d_in[3];   // (8,320,320,1)
    const float* tths   = (const float*)d_in[4];   // (8,16,1)
    float* out = (float*)d_out;                    // (8,)

    ImgKeys keys;
    for (int b = 0; b < BB; b++)
        tf2x32(0u, 42u, 0u, (u32)b, keys.k0[b], keys.k1[b]);

    k_candidates<<<dim3(HW / 256, BB), 256>>>(confs, rects, keys);
    k_compact<<<dim3(32, BB), 256>>>();
    k_select_sum<<<BB, 1024>>>(boxes, rects, thetas, tths, out);
}